// round 15
// baseline (speedup 1.0000x reference)
#include <cuda_runtime.h>

#define WIDTH    512
#define HEIGHT   512
#define TH       128
#define TH_IN    (TH + 10)            // 138 input rows per strip
#define STRIPS   (HEIGHT / TH)        // 4
#define COLBLK   4                    // 128-col block strips
#define CHANNELS 96                   // 32 * 3
#define NBLK     (STRIPS * COLBLK * CHANNELS) // 1536

#define C1v 1.0e-4f
#define C2v 9.0e-4f

// Gaussian(sigma=1.5, k=11) weights; compile-time indices -> FFMA-imm (rt=1).
#define DECL_KW \
    constexpr float KW[11] = { \
        0.00102838f, 0.00759876f, 0.03600078f, 0.10936081f, 0.21300554f, \
        0.26601173f, \
        0.21300554f, 0.10936081f, 0.03600078f, 0.00759876f, 0.00102838f }

__device__ float g_partial[NBLK];
__device__ int   g_count = 0;

__global__ void __launch_bounds__(128, 8)
ssim_main(const float* __restrict__ pred, const float* __restrict__ targ,
          float* __restrict__ out) {
    DECL_KW;
    // Warp-private staging: 42 (e,d) float2 per warp per buffer
    // (32 own cols + 5 halo each side), double-buffered; only __syncwarp().
    __shared__ float2 sW[2][4][44];
    __shared__ float  wsum[4];
    __shared__ double dsh[128];
    __shared__ int    sIsLast;

    const int tid = threadIdx.x;
    const int w   = tid >> 5;
    const int l   = tid & 31;
    const int bx  = blockIdx.x;          // 0..15: 4 colblocks x 4 strips
    const int ch  = blockIdx.y;
    const int y0      = (bx >> 2) * TH;
    const int colbase = (bx & 3) * 128 + w * 32;
    const int c0 = colbase + l;

    // halo assignment for lanes 0..9
    int hidx = 0, chalo = 0; bool hval = false;
    if (l < 5)       { chalo = colbase - 5 + l;  hidx = l;      hval = (chalo >= 0); }
    else if (l < 10) { chalo = colbase + 27 + l; hidx = 32 + l; hval = (chalo < WIDTH); }

    const float* __restrict__ P = pred + (size_t)ch * (WIDTH * HEIGHT);
    const float* __restrict__ T = targ + (size_t)ch * (WIDTH * HEIGHT);

    // vertical ring over 11 horizontal-conv result rows (scalar, 44 regs)
    float rE[11], rD[11], rE2[11], rD2[11];
    float acc = 0.f;

    // 1-deep prefetch (row k=0, abs y0-5)
    float pN = 0.f, tN = 0.f, pHN = 0.f, tHN = 0.f;
    {
        const int r = y0 - 5;
        if ((unsigned)r < (unsigned)HEIGHT) {
            pN = P[r * WIDTH + c0];
            tN = T[r * WIDTH + c0];
            if (hval) { pHN = P[r * WIDTH + chalo]; tHN = T[r * WIDTH + chalo]; }
        }
    }

    // k = 0..TH_IN-1; ring slot = k % 11 (kc % 11 == 0 keeps it compile-time)
    #pragma unroll 1
    for (int kc = 0; kc < TH_IN; kc += 11) {
        #pragma unroll
        for (int u = 0; u < 11; u++) {
            const int k = kc + u;
            if (k >= TH_IN) break;   // uniform

            const float p = pN, t = tN, ph = pHN, th = tHN;
            if (k + 1 < TH_IN) {     // prefetch abs row y0-4+k
                const int r = y0 - 4 + k;
                if ((unsigned)r < (unsigned)HEIGHT) {
                    pN = P[r * WIDTH + c0];
                    tN = T[r * WIDTH + c0];
                    if (hval) { pHN = P[r * WIDTH + chalo]; tHN = T[r * WIDTH + chalo]; }
                    else      { pHN = 0.f; tHN = 0.f; }
                } else { pN = 0.f; tN = 0.f; pHN = 0.f; tHN = 0.f; }
            }

            // stage (e,d); warp-private, so only syncwarp needed
            const int buf = k & 1;
            sW[buf][w][5 + l] = make_float2(p + t, p - t);
            if (l < 10) sW[buf][w][hidx] = make_float2(ph + th, ph - th);
            __syncwarp();

            // horizontal conv: 11 LDS.64 + 22 FMUL + 44 FFMA-imm
            float hE = 0.f, hD = 0.f, hE2 = 0.f, hD2 = 0.f;
            #pragma unroll
            for (int i = 0; i < 11; i++) {
                const float2 v = sW[buf][w][l + i];
                hE  = fmaf(v.x,       KW[i], hE);
                hD  = fmaf(v.y,       KW[i], hD);
                hE2 = fmaf(v.x * v.x, KW[i], hE2);
                hD2 = fmaf(v.y * v.y, KW[i], hD2);
            }
            rE[u] = hE; rD[u] = hD; rE2[u] = hE2; rD2[u] = hD2;

            // vertical conv + SSIM once ring full (output row k-10)
            if (k >= 10) {
                float me = 0.f, md = 0.f, ce2 = 0.f, cd2 = 0.f;
                #pragma unroll
                for (int i = 0; i < 11; i++) {
                    const int s = (u + 1 + i) % 11;
                    me  = fmaf(rE[s],  KW[i], me);
                    md  = fmaf(rD[s],  KW[i], md);
                    ce2 = fmaf(rE2[s], KW[i], ce2);
                    cd2 = fmaf(rD2[s], KW[i], cd2);
                }
                const float A  = me * me;
                const float B  = md * md;
                const float t1 = A - B;
                const float t2 = A + B;
                const float n1 = fmaf(0.5f, t1, C1v);
                const float d1 = fmaf(0.5f, t2, C1v);
                const float n2 = fmaf(0.5f, (ce2 - cd2) - t1, C2v);
                const float d2 = fmaf(0.5f, (ce2 + cd2) - t2, C2v);
                acc += __fdividef(n1 * n2, d1 * d2);
            }
        }
    }

    // deterministic block reduction (one barrier, at the end)
    #pragma unroll
    for (int o = 16; o > 0; o >>= 1)
        acc += __shfl_down_sync(0xffffffffu, acc, o);
    if (l == 0) wsum[w] = acc;
    __syncthreads();
    if (tid < 32) {
        float v = (l < 4) ? wsum[l] : 0.f;
        v += __shfl_down_sync(0xffffffffu, v, 2);
        v += __shfl_down_sync(0xffffffffu, v, 1);
        if (l == 0)
            g_partial[blockIdx.y * (STRIPS * COLBLK) + blockIdx.x] = v;
    }

    // deterministic last-block final reduction (fp64, fixed order)
    if (tid == 0) {
        __threadfence();
        const int n = atomicAdd(&g_count, 1);
        sIsLast = (n == NBLK - 1);
    }
    __syncthreads();
    if (sIsLast) {
        __threadfence();
        double s = 0.0;
        for (int i = tid; i < NBLK; i += 128)
            s += (double)g_partial[i];
        dsh[tid] = s;
        __syncthreads();
        #pragma unroll 1
        for (int o = 64; o > 0; o >>= 1) {
            if (tid < o) dsh[tid] += dsh[tid + o];
            __syncthreads();
        }
        if (tid == 0) {
            out[0] = (float)(1.0 - dsh[0] / 25165824.0);  // 32*3*512*512
            g_count = 0;  // reset for next graph replay
        }
    }
}

extern "C" void kernel_launch(void* const* d_in, const int* in_sizes, int n_in,
                              void* d_out, int out_size) {
    const float* pred = (const float*)d_in[0];
    const float* targ = (const float*)d_in[1];
    ssim_main<<<dim3(STRIPS * COLBLK, CHANNELS), 128>>>(pred, targ, (float*)d_out);
}

// round 16
// speedup vs baseline: 1.0336x; 1.0336x over previous
#include <cuda_runtime.h>

#define WIDTH    512
#define HEIGHT   512
#define NSTRIPS  6                    // 85/86-row strips: waves = 1152/592 ~= 2.0
#define HALVES   2
#define CHANNELS 96                   // 32 * 3
#define NBLK     (NSTRIPS * HALVES * CHANNELS) // 1152

#define C1v 1.0e-4f
#define C2v 9.0e-4f

// Gaussian(sigma=1.5, k=11) weights; compile-time indices -> FFMA-imm (rt=1).
#define DECL_KW \
    constexpr float KW[11] = { \
        0.00102838f, 0.00759876f, 0.03600078f, 0.10936081f, 0.21300554f, \
        0.26601173f, \
        0.21300554f, 0.10936081f, 0.03600078f, 0.00759876f, 0.00102838f }

__device__ float g_partial[NBLK];
__device__ int   g_count = 0;

__global__ void __launch_bounds__(256, 4)
ssim_main(const float* __restrict__ pred, const float* __restrict__ targ,
          float* __restrict__ out) {
    DECL_KW;
    // Warp-private staging: 42 (e,d) float2 per warp per buffer
    // (32 own cols + 5 halo each side), double-buffered; only __syncwarp().
    __shared__ float2 sW[2][8][44];
    __shared__ float  wsum[8];
    __shared__ double dsh[256];
    __shared__ int    sIsLast;

    const int tid  = threadIdx.x;
    const int w    = tid >> 5;
    const int l    = tid & 31;
    const int half  = blockIdx.x & 1;
    const int strip = blockIdx.x >> 1;       // 0..5
    const int ch    = blockIdx.y;
    const int y0    = (strip * 256) / 3;     // 0,85,170,256,341,426
    const int y1    = ((strip + 1) * 256) / 3;
    const int TH_IN = (y1 - y0) + 10;        // 95 or 96 input rows (warp-uniform)
    const int colbase = half * 256 + w * 32;
    const int c0 = colbase + l;

    // halo assignment for lanes 0..9
    int hidx = 0, chalo = 0; bool hval = false;
    if (l < 5)       { chalo = colbase - 5 + l;  hidx = l;      hval = (chalo >= 0); }
    else if (l < 10) { chalo = colbase + 27 + l; hidx = 32 + l; hval = (chalo < WIDTH); }

    const float* __restrict__ P = pred + (size_t)ch * (WIDTH * HEIGHT);
    const float* __restrict__ T = targ + (size_t)ch * (WIDTH * HEIGHT);

    // vertical ring over 11 horizontal-conv result rows (scalar, 44 regs)
    float rE[11], rD[11], rE2[11], rD2[11];
    float acc = 0.f;

    // 1-deep prefetch (row k=0, abs y0-5)
    float pN = 0.f, tN = 0.f, pHN = 0.f, tHN = 0.f;
    {
        const int r = y0 - 5;
        if ((unsigned)r < (unsigned)HEIGHT) {
            pN = P[r * WIDTH + c0];
            tN = T[r * WIDTH + c0];
            if (hval) { pHN = P[r * WIDTH + chalo]; tHN = T[r * WIDTH + chalo]; }
        }
    }

    // k = 0..TH_IN-1; ring slot = k % 11 (kc % 11 == 0 keeps it compile-time)
    #pragma unroll 1
    for (int kc = 0; kc < TH_IN; kc += 11) {
        #pragma unroll
        for (int u = 0; u < 11; u++) {
            const int k = kc + u;
            if (k >= TH_IN) break;   // uniform

            const float p = pN, t = tN, ph = pHN, th = tHN;
            if (k + 1 < TH_IN) {     // prefetch abs row y0-4+k
                const int r = y0 - 4 + k;
                if ((unsigned)r < (unsigned)HEIGHT) {
                    pN = P[r * WIDTH + c0];
                    tN = T[r * WIDTH + c0];
                    if (hval) { pHN = P[r * WIDTH + chalo]; tHN = T[r * WIDTH + chalo]; }
                    else      { pHN = 0.f; tHN = 0.f; }
                } else { pN = 0.f; tN = 0.f; pHN = 0.f; tHN = 0.f; }
            }

            // stage (e,d); warp-private, so only syncwarp needed
            const int buf = k & 1;
            sW[buf][w][5 + l] = make_float2(p + t, p - t);
            if (l < 10) sW[buf][w][hidx] = make_float2(ph + th, ph - th);
            __syncwarp();

            // horizontal conv: 11 LDS.64 + 22 FMUL + 44 FFMA-imm
            float hE = 0.f, hD = 0.f, hE2 = 0.f, hD2 = 0.f;
            #pragma unroll
            for (int i = 0; i < 11; i++) {
                const float2 v = sW[buf][w][l + i];
                hE  = fmaf(v.x,       KW[i], hE);
                hD  = fmaf(v.y,       KW[i], hD);
                hE2 = fmaf(v.x * v.x, KW[i], hE2);
                hD2 = fmaf(v.y * v.y, KW[i], hD2);
            }
            rE[u] = hE; rD[u] = hD; rE2[u] = hE2; rD2[u] = hD2;

            // vertical conv + SSIM once ring full (output row k-10)
            if (k >= 10) {
                float me = 0.f, md = 0.f, ce2 = 0.f, cd2 = 0.f;
                #pragma unroll
                for (int i = 0; i < 11; i++) {
                    const int s = (u + 1 + i) % 11;
                    me  = fmaf(rE[s],  KW[i], me);
                    md  = fmaf(rD[s],  KW[i], md);
                    ce2 = fmaf(rE2[s], KW[i], ce2);
                    cd2 = fmaf(rD2[s], KW[i], cd2);
                }
                const float A  = me * me;
                const float B  = md * md;
                const float t1 = A - B;
                const float t2 = A + B;
                const float n1 = fmaf(0.5f, t1, C1v);
                const float d1 = fmaf(0.5f, t2, C1v);
                const float n2 = fmaf(0.5f, (ce2 - cd2) - t1, C2v);
                const float d2 = fmaf(0.5f, (ce2 + cd2) - t2, C2v);
                acc += __fdividef(n1 * n2, d1 * d2);
            }
        }
    }

    // deterministic block reduction (one barrier, at the end)
    #pragma unroll
    for (int o = 16; o > 0; o >>= 1)
        acc += __shfl_down_sync(0xffffffffu, acc, o);
    if (l == 0) wsum[w] = acc;
    __syncthreads();
    if (tid < 32) {
        float v = (l < 8) ? wsum[l] : 0.f;
        #pragma unroll
        for (int o = 4; o > 0; o >>= 1)
            v += __shfl_down_sync(0xffffffffu, v, o);
        if (l == 0)
            g_partial[blockIdx.y * (NSTRIPS * HALVES) + blockIdx.x] = v;
    }

    // deterministic last-block final reduction (fp64, fixed order)
    if (tid == 0) {
        __threadfence();
        const int n = atomicAdd(&g_count, 1);
        sIsLast = (n == NBLK - 1);
    }
    __syncthreads();
    if (sIsLast) {
        __threadfence();
        double s = 0.0;
        for (int i = tid; i < NBLK; i += 256)
            s += (double)g_partial[i];
        dsh[tid] = s;
        __syncthreads();
        #pragma unroll 1
        for (int o = 128; o > 0; o >>= 1) {
            if (tid < o) dsh[tid] += dsh[tid + o];
            __syncthreads();
        }
        if (tid == 0) {
            out[0] = (float)(1.0 - dsh[0] / 25165824.0);  // 32*3*512*512
            g_count = 0;  // reset for next graph replay
        }
    }
}

extern "C" void kernel_launch(void* const* d_in, const int* in_sizes, int n_in,
                              void* d_out, int out_size) {
    const float* pred = (const float*)d_in[0];
    const float* targ = (const float*)d_in[1];
    ssim_main<<<dim3(NSTRIPS * HALVES, CHANNELS), 256>>>(pred, targ, (float*)d_out);
}